// round 3
// baseline (speedup 1.0000x reference)
#include <cuda_runtime.h>
#include <cstdint>

#define N_NODES 100000
#define N_EDGES 1600000
#define N_GRAPHS 256
#define IN_C 64
#define HID 128
#define BN_EPS 1e-5f
#define CK 32
#define RSTR 132   // transposed-buffer row stride (128 rows + pad), 16B-aligned

// ---------------- scratch (device globals; no allocation) ----------------
__device__ float g_Z0[(size_t)N_NODES * HID];
__device__ float g_Z1[(size_t)N_NODES * HID];
__device__ float g_AGG[(size_t)N_NODES * HID];
__device__ float g_STATS[2 * HID];
__device__ float g_SCALE[3 * HID];
__device__ float g_SHIFT[3 * HID];
__device__ float g_POOL[N_GRAPHS * HID];
__device__ float g_CINV[N_GRAPHS];

// ---------------- small utility kernels ----------------
__global__ void zero_kernel(float* p, int n) {
    int i = blockIdx.x * blockDim.x + threadIdx.x;
    if (i < n) p[i] = 0.f;
}
__global__ void zero4_kernel(float4* p, int n4) {
    int i = blockIdx.x * blockDim.x + threadIdx.x;
    if (i < n4) p[i] = make_float4(0.f, 0.f, 0.f, 0.f);
}

// ---------------- scatter: agg[dst] += bnrelu?(z[src]) ----------------
template <int C, bool BN>
__global__ void scatter_kernel(const int* __restrict__ ei,
                               const float* __restrict__ zsrc,
                               const float* __restrict__ scale,
                               const float* __restrict__ shift,
                               float* __restrict__ agg) {
    const int CH = C / 4;
    long long idx = (long long)blockIdx.x * blockDim.x + threadIdx.x;
    if (idx >= (long long)N_EDGES * CH) return;
    int e = (int)(idx / CH);
    int c = ((int)idx % CH) * 4;
    int s = ei[e];
    int d = ei[N_EDGES + e];
    float4 v = *(const float4*)(zsrc + (long long)s * C + c);
    if (BN) {
        float4 sc = *(const float4*)(scale + c);
        float4 sh = *(const float4*)(shift + c);
        v.x = fmaxf(fmaf(v.x, sc.x, sh.x), 0.f);
        v.y = fmaxf(fmaf(v.y, sc.y, sh.y), 0.f);
        v.z = fmaxf(fmaf(v.z, sc.z, sh.z), 0.f);
        v.w = fmaxf(fmaf(v.w, sc.w, sh.w), 0.f);
    }
    float* p = agg + (long long)d * C + c;
    asm volatile("red.global.add.v4.f32 [%0], {%1,%2,%3,%4};"
                 :: "l"(p), "f"(v.x), "f"(v.y), "f"(v.z), "f"(v.w) : "memory");
}

// ---------------- fused MLP ----------------
// z_in = bnrelu?(self) + agg ; zout = relu(z_in@w1+b1)@w2+b2 ; BN col stats fused.
// 128x128 tile / block, 256 threads, 8x8 register tiles.
// SMEM: region (16896 fl) = szT (z transposed, [k][row]) during GEMM1,
//       reused as shT (hidden transposed, [hcol][row]) during GEMM2.
//       sw: one 32x128 weight chunk, register-prefetched pipeline.
template <int CIN, bool SELFBN>
__global__ __launch_bounds__(256, 2)
void mlp_kernel(const float* __restrict__ agg, const float* __restrict__ self,
                const float* __restrict__ scale, const float* __restrict__ shift,
                const float* __restrict__ w1, const float* __restrict__ b1,
                const float* __restrict__ w2, const float* __restrict__ b2,
                float* __restrict__ zout, float* __restrict__ stats) {
    extern __shared__ float sm[];
    float* region = sm;                  // 16896 floats (szT | shT union)
    float* sw     = sm + 128 * RSTR;     // CK*HID = 4096
    float* ssum   = sw + CK * HID;       // HID
    float* ssq    = ssum + HID;          // HID

    const int tid  = threadIdx.x;
    const int row0 = blockIdx.x * 128;
    const int tx = tid & 15, ty = tid >> 4;
    const int c0 = tx * 4;
    const int c1 = 64 + tx * 4;
    const int r0 = ty * 8;

    if (tid < HID) { ssum[tid] = 0.f; ssq[tid] = 0.f; }

    // ---- stage full z tile, transposed: szT[k*RSTR + r] ----
    {
        const int QPR = CIN / 4;                 // float4 quads per row
        const int TOT = 128 * QPR;               // total float4
        #pragma unroll
        for (int t = 0; t < TOT / 256; t++) {
            int i = t * 256 + tid;
            int r = i / QPR, q = i % QPR;
            int gr = row0 + r;
            float4 v = make_float4(0.f, 0.f, 0.f, 0.f);
            if (gr < N_NODES) {
                float4 a = *(const float4*)(agg + (size_t)gr * CIN + q * 4);
                float4 s = *(const float4*)(self + (size_t)gr * CIN + q * 4);
                if (SELFBN) {
                    float4 sc = *(const float4*)(scale + q * 4);
                    float4 sh = *(const float4*)(shift + q * 4);
                    v.x = a.x + fmaxf(fmaf(s.x, sc.x, sh.x), 0.f);
                    v.y = a.y + fmaxf(fmaf(s.y, sc.y, sh.y), 0.f);
                    v.z = a.z + fmaxf(fmaf(s.z, sc.z, sh.z), 0.f);
                    v.w = a.w + fmaxf(fmaf(s.w, sc.w, sh.w), 0.f);
                } else {
                    v.x = a.x + s.x; v.y = a.y + s.y; v.z = a.z + s.z; v.w = a.w + s.w;
                }
            }
            region[(q * 4 + 0) * RSTR + r] = v.x;
            region[(q * 4 + 1) * RSTR + r] = v.y;
            region[(q * 4 + 2) * RSTR + r] = v.z;
            region[(q * 4 + 3) * RSTR + r] = v.w;
        }
    }

    float acc[8][8];
    float4 wp0, wp1, wp2, wp3;   // weight prefetch regs

    // prefetch w1 chunk 0
    wp0 = ((const float4*)w1)[0 * 256 + tid];
    wp1 = ((const float4*)w1)[1 * 256 + tid];
    wp2 = ((const float4*)w1)[2 * 256 + tid];
    wp3 = ((const float4*)w1)[3 * 256 + tid];

    // ======== GEMM1 ========
    #pragma unroll
    for (int i = 0; i < 8; i++) {
        #pragma unroll
        for (int j = 0; j < 4; j++) { acc[i][j] = b1[c0 + j]; acc[i][4 + j] = b1[c1 + j]; }
    }
    const int NKC = CIN / CK;
    for (int kc = 0; kc < NKC; kc++) {
        __syncthreads();                               // prev chunk's sw reads done (kc=0: no-op role)
        ((float4*)sw)[0 * 256 + tid] = wp0;
        ((float4*)sw)[1 * 256 + tid] = wp1;
        ((float4*)sw)[2 * 256 + tid] = wp2;
        ((float4*)sw)[3 * 256 + tid] = wp3;
        __syncthreads();                               // sw + (kc=0) szT visible
        {   // prefetch next chunk (w1 tail, then w2 chunk 0)
            const float4* nxt = (kc + 1 < NKC) ? ((const float4*)w1) + (kc + 1) * 1024
                                               : ((const float4*)w2);
            wp0 = nxt[0 * 256 + tid];
            wp1 = nxt[1 * 256 + tid];
            wp2 = nxt[2 * 256 + tid];
            wp3 = nxt[3 * 256 + tid];
        }
        #pragma unroll 4
        for (int k = 0; k < CK; k++) {
            int kk = kc * CK + k;
            float4 z0 = *(const float4*)&region[kk * RSTR + r0];
            float4 z1 = *(const float4*)&region[kk * RSTR + r0 + 4];
            float4 wa = *(const float4*)&sw[k * HID + c0];
            float4 wb = *(const float4*)&sw[k * HID + c1];
            float zr[8] = {z0.x, z0.y, z0.z, z0.w, z1.x, z1.y, z1.z, z1.w};
            #pragma unroll
            for (int i = 0; i < 8; i++) {
                float z = zr[i];
                acc[i][0] = fmaf(z, wa.x, acc[i][0]);
                acc[i][1] = fmaf(z, wa.y, acc[i][1]);
                acc[i][2] = fmaf(z, wa.z, acc[i][2]);
                acc[i][3] = fmaf(z, wa.w, acc[i][3]);
                acc[i][4] = fmaf(z, wb.x, acc[i][4]);
                acc[i][5] = fmaf(z, wb.y, acc[i][5]);
                acc[i][6] = fmaf(z, wb.z, acc[i][6]);
                acc[i][7] = fmaf(z, wb.w, acc[i][7]);
            }
        }
    }

    __syncthreads();   // all szT reads done; region can become shT

    // relu + store hidden transposed: shT[c*RSTR + r], two STS.128 per owned col
    #pragma unroll
    for (int j = 0; j < 4; j++) {
        float4 ha = make_float4(fmaxf(acc[0][j], 0.f), fmaxf(acc[1][j], 0.f),
                                fmaxf(acc[2][j], 0.f), fmaxf(acc[3][j], 0.f));
        float4 hb = make_float4(fmaxf(acc[4][j], 0.f), fmaxf(acc[5][j], 0.f),
                                fmaxf(acc[6][j], 0.f), fmaxf(acc[7][j], 0.f));
        *(float4*)&region[(c0 + j) * RSTR + r0]     = ha;
        *(float4*)&region[(c0 + j) * RSTR + r0 + 4] = hb;
        float4 hc = make_float4(fmaxf(acc[0][4 + j], 0.f), fmaxf(acc[1][4 + j], 0.f),
                                fmaxf(acc[2][4 + j], 0.f), fmaxf(acc[3][4 + j], 0.f));
        float4 hd = make_float4(fmaxf(acc[4][4 + j], 0.f), fmaxf(acc[5][4 + j], 0.f),
                                fmaxf(acc[6][4 + j], 0.f), fmaxf(acc[7][4 + j], 0.f));
        *(float4*)&region[(c1 + j) * RSTR + r0]     = hc;
        *(float4*)&region[(c1 + j) * RSTR + r0 + 4] = hd;
    }

    // ======== GEMM2 ========
    #pragma unroll
    for (int i = 0; i < 8; i++) {
        #pragma unroll
        for (int j = 0; j < 4; j++) { acc[i][j] = b2[c0 + j]; acc[i][4 + j] = b2[c1 + j]; }
    }
    for (int kc = 0; kc < HID / CK; kc++) {
        __syncthreads();                               // prev sw reads + (kc=0) shT stores done
        ((float4*)sw)[0 * 256 + tid] = wp0;
        ((float4*)sw)[1 * 256 + tid] = wp1;
        ((float4*)sw)[2 * 256 + tid] = wp2;
        ((float4*)sw)[3 * 256 + tid] = wp3;
        __syncthreads();
        if (kc + 1 < HID / CK) {
            const float4* nxt = ((const float4*)w2) + (kc + 1) * 1024;
            wp0 = nxt[0 * 256 + tid];
            wp1 = nxt[1 * 256 + tid];
            wp2 = nxt[2 * 256 + tid];
            wp3 = nxt[3 * 256 + tid];
        }
        #pragma unroll 4
        for (int k = 0; k < CK; k++) {
            int kk = kc * CK + k;
            float4 h0 = *(const float4*)&region[kk * RSTR + r0];
            float4 h1 = *(const float4*)&region[kk * RSTR + r0 + 4];
            float4 wa = *(const float4*)&sw[k * HID + c0];
            float4 wb = *(const float4*)&sw[k * HID + c1];
            float hr[8] = {h0.x, h0.y, h0.z, h0.w, h1.x, h1.y, h1.z, h1.w};
            #pragma unroll
            for (int i = 0; i < 8; i++) {
                float h = hr[i];
                acc[i][0] = fmaf(h, wa.x, acc[i][0]);
                acc[i][1] = fmaf(h, wa.y, acc[i][1]);
                acc[i][2] = fmaf(h, wa.z, acc[i][2]);
                acc[i][3] = fmaf(h, wa.w, acc[i][3]);
                acc[i][4] = fmaf(h, wb.x, acc[i][4]);
                acc[i][5] = fmaf(h, wb.y, acc[i][5]);
                acc[i][6] = fmaf(h, wb.z, acc[i][6]);
                acc[i][7] = fmaf(h, wb.w, acc[i][7]);
            }
        }
    }

    // ======== epilogue: store pre-BN z, accumulate BN column stats ========
    float s[8], q[8];
    #pragma unroll
    for (int j = 0; j < 8; j++) { s[j] = 0.f; q[j] = 0.f; }

    #pragma unroll
    for (int i = 0; i < 8; i++) {
        int gr = row0 + r0 + i;
        if (gr < N_NODES) {
            *(float4*)&zout[(size_t)gr * HID + c0] =
                make_float4(acc[i][0], acc[i][1], acc[i][2], acc[i][3]);
            *(float4*)&zout[(size_t)gr * HID + c1] =
                make_float4(acc[i][4], acc[i][5], acc[i][6], acc[i][7]);
            #pragma unroll
            for (int j = 0; j < 8; j++) {
                float v = acc[i][j];
                s[j] += v; q[j] += v * v;
            }
        }
    }
    #pragma unroll
    for (int j = 0; j < 4; j++) {
        atomicAdd(&ssum[c0 + j], s[j]);
        atomicAdd(&ssq[c0 + j], q[j]);
        atomicAdd(&ssum[c1 + j], s[4 + j]);
        atomicAdd(&ssq[c1 + j], q[4 + j]);
    }
    __syncthreads();
    if (tid < HID) {
        atomicAdd(&stats[tid], ssum[tid]);
        atomicAdd(&stats[HID + tid], ssq[tid]);
    }
}

// ---------------- BN finalize ----------------
__global__ void bn_finalize_kernel(const float* __restrict__ gamma,
                                   const float* __restrict__ beta,
                                   const float* __restrict__ stats,
                                   float* __restrict__ scale,
                                   float* __restrict__ shift) {
    int c = threadIdx.x;
    float mean = stats[c] * (1.f / N_NODES);
    float var  = stats[HID + c] * (1.f / N_NODES) - mean * mean;
    float inv  = rsqrtf(var + BN_EPS);
    float sc   = gamma[c] * inv;
    scale[c] = sc;
    shift[c] = beta[c] - mean * sc;
}

// ---------------- mean pool with fused BN+relu (batch sorted) ----------------
__global__ void pool_kernel(const float* __restrict__ z, const int* __restrict__ batch,
                            const float* __restrict__ scale, const float* __restrict__ shift,
                            float* __restrict__ pool) {
    __shared__ int sb[256];
    int r0  = blockIdx.x * 256;
    int tid = threadIdx.x;  // 128 threads, one column each
    for (int i = tid; i < 256; i += 128) {
        int gr = r0 + i;
        sb[i] = (gr < N_NODES) ? batch[gr] : -1;
    }
    __syncthreads();
    int c = tid;
    float sc = scale[c], sh = shift[c];
    float sum = 0.f;
    int cur = sb[0];
    for (int i = 0; i < 256; i++) {
        int gr = r0 + i;
        if (gr >= N_NODES) break;
        int b = sb[i];
        if (b != cur) {
            atomicAdd(&pool[cur * HID + c], sum);
            sum = 0.f; cur = b;
        }
        sum += fmaxf(fmaf(z[(long long)gr * HID + c], sc, sh), 0.f);
    }
    if (cur >= 0) atomicAdd(&pool[cur * HID + c], sum);
}

// ---------------- per-graph counts via binary search ----------------
__global__ void count_kernel(const int* __restrict__ batch, float* __restrict__ cinv) {
    int g = threadIdx.x;
    int lo = 0, hi = N_NODES;
    while (lo < hi) { int m = (lo + hi) >> 1; if (batch[m] < g) lo = m + 1; else hi = m; }
    int a = lo;
    lo = 0; hi = N_NODES;
    while (lo < hi) { int m = (lo + hi) >> 1; if (batch[m] < g + 1) lo = m + 1; else hi = m; }
    float cnt = (float)(lo - a);
    cinv[g] = 1.f / fmaxf(cnt, 1.f);
}

// ---------------- final projection ----------------
__global__ void proj_kernel(const float* __restrict__ w, const float* __restrict__ b,
                            const float* __restrict__ pool, const float* __restrict__ cinv,
                            float* __restrict__ out) {
    __shared__ float hg[HID];
    int g = blockIdx.x, t = threadIdx.x;
    hg[t] = pool[g * HID + t] * cinv[g];
    __syncthreads();
    float acc = b[t];
    #pragma unroll 8
    for (int k = 0; k < HID; k++) acc = fmaf(hg[k], w[k * HID + t], acc);
    out[g * HID + t] = acc;
}

// ---------------- host orchestration ----------------
static void* sym(const void* s) {
    void* p = nullptr;
    cudaGetSymbolAddress(&p, s);
    return p;
}

extern "C" void kernel_launch(void* const* d_in, const int* in_sizes, int n_in,
                              void* d_out, int out_size) {
    const float* x     = (const float*)d_in[0];
    const int*   ei    = (const int*)d_in[1];
    const int*   batch = (const int*)d_in[2];
    const float* L[3][6];
    for (int l = 0; l < 3; l++)
        for (int k = 0; k < 6; k++) L[l][k] = (const float*)d_in[3 + 6 * l + k];
    const float* proj_w = (const float*)d_in[21];
    const float* proj_b = (const float*)d_in[22];
    float* out = (float*)d_out;

    float* Z0    = (float*)sym(g_Z0);
    float* Z1    = (float*)sym(g_Z1);
    float* AGG   = (float*)sym(g_AGG);
    float* STATS = (float*)sym(g_STATS);
    float* SCALE = (float*)sym(g_SCALE);
    float* SHIFT = (float*)sym(g_SHIFT);
    float* POOL  = (float*)sym(g_POOL);
    float* CINV  = (float*)sym(g_CINV);

    const int smemMlp = (128 * RSTR + CK * HID + 2 * HID) * 4;
    cudaFuncSetAttribute(mlp_kernel<IN_C, false>, cudaFuncAttributeMaxDynamicSharedMemorySize, smemMlp);
    cudaFuncSetAttribute(mlp_kernel<HID, true>,   cudaFuncAttributeMaxDynamicSharedMemorySize, smemMlp);

    const int mlpBlocks = (N_NODES + 127) / 128;
    const int agg64_4   = N_NODES * IN_C / 4;
    const int agg128_4  = N_NODES * HID / 4;

    // ---- layer 0 (CIN=64): agg = scatter(x); z_in = x + agg ----
    zero4_kernel<<<(agg64_4 + 255) / 256, 256>>>((float4*)AGG, agg64_4);
    {
        long long st = (long long)N_EDGES * (IN_C / 4);
        scatter_kernel<IN_C, false><<<(int)((st + 255) / 256), 256>>>(ei, x, nullptr, nullptr, AGG);
    }
    zero_kernel<<<1, 256>>>(STATS, 2 * HID);
    mlp_kernel<IN_C, false><<<mlpBlocks, 256, smemMlp>>>(
        AGG, x, nullptr, nullptr, L[0][0], L[0][1], L[0][2], L[0][3], Z0, STATS);
    bn_finalize_kernel<<<1, HID>>>(L[0][4], L[0][5], STATS, SCALE, SHIFT);

    // ---- layers 1,2 (CIN=128) ----
    const float* zprev = Z0;
    float* zcur = Z1;
    for (int l = 1; l < 3; l++) {
        const float* sc = SCALE + (l - 1) * HID;
        const float* sh = SHIFT + (l - 1) * HID;
        zero4_kernel<<<(agg128_4 + 255) / 256, 256>>>((float4*)AGG, agg128_4);
        long long st = (long long)N_EDGES * (HID / 4);
        scatter_kernel<HID, true><<<(int)((st + 255) / 256), 256>>>(ei, zprev, sc, sh, AGG);
        zero_kernel<<<1, 256>>>(STATS, 2 * HID);
        mlp_kernel<HID, true><<<mlpBlocks, 256, smemMlp>>>(
            AGG, zprev, sc, sh, L[l][0], L[l][1], L[l][2], L[l][3], zcur, STATS);
        bn_finalize_kernel<<<1, HID>>>(L[l][4], L[l][5], STATS, SCALE + l * HID, SHIFT + l * HID);
        const float* t = zprev; zprev = zcur; zcur = (float*)t;
    }

    // ---- pool + projection (BN of layer 2 fused into pool) ----
    zero_kernel<<<(N_GRAPHS * HID + 255) / 256, 256>>>(POOL, N_GRAPHS * HID);
    pool_kernel<<<(N_NODES + 255) / 256, 128>>>(zprev, batch, SCALE + 2 * HID, SHIFT + 2 * HID, POOL);
    count_kernel<<<1, N_GRAPHS>>>(batch, CINV);
    proj_kernel<<<N_GRAPHS, HID>>>(proj_w, proj_b, POOL, CINV, out);
}

// round 4
// speedup vs baseline: 1.0644x; 1.0644x over previous
#include <cuda_runtime.h>
#include <cstdint>

#define N_NODES 100000
#define N_EDGES 1600000
#define N_GRAPHS 256
#define IN_C 64
#define HID 128
#define BN_EPS 1e-5f
#define CK 32           // k-chunk
#define SZ_STR 36       // z-chunk row stride (floats)
#define SH_STR 132      // hidden row stride (floats)

typedef unsigned long long u64t;

// ---- packed fp32x2 helpers (FFMA2 — only reachable via PTX) ----
__device__ __forceinline__ u64t pk2(float lo, float hi) {
    u64t r; asm("mov.b64 %0,{%1,%2};" : "=l"(r) : "f"(lo), "f"(hi)); return r;
}
__device__ __forceinline__ u64t pkd(float v) {
    u64t r; asm("mov.b64 %0,{%1,%1};" : "=l"(r) : "f"(v)); return r;
}
__device__ __forceinline__ void upk(u64t p, float& lo, float& hi) {
    asm("mov.b64 {%0,%1},%2;" : "=f"(lo), "=f"(hi) : "l"(p));
}
__device__ __forceinline__ u64t ffma2(u64t a, u64t b, u64t c) {
    u64t d; asm("fma.rn.f32x2 %0,%1,%2,%3;" : "=l"(d) : "l"(a), "l"(b), "l"(c)); return d;
}

// ---------------- scratch (device globals; no allocation) ----------------
__device__ float g_H[(size_t)N_NODES * HID];
__device__ float g_AGG[(size_t)N_NODES * HID];
__device__ float g_Z[(size_t)N_NODES * HID];
__device__ float g_STATS[2 * HID];
__device__ float g_SCALE[HID];
__device__ float g_SHIFT[HID];
__device__ float g_POOL[N_GRAPHS * HID];
__device__ float g_CINV[N_GRAPHS];

// ---------------- small utility kernels ----------------
__global__ void zero_kernel(float* p, int n) {
    int i = blockIdx.x * blockDim.x + threadIdx.x;
    if (i < n) p[i] = 0.f;
}
__global__ void copy4_kernel(float4* dst, const float4* __restrict__ src, int n4) {
    int i = blockIdx.x * blockDim.x + threadIdx.x;
    if (i < n4) dst[i] = src[i];
}

// ---------------- scatter: agg[dst] += h[src] (vector red) ----------------
template <int C>
__global__ void scatter_kernel(const int* __restrict__ ei,
                               const float* __restrict__ h,
                               float* __restrict__ agg) {
    const int CH = C / 4;
    long long idx = (long long)blockIdx.x * blockDim.x + threadIdx.x;
    if (idx >= (long long)N_EDGES * CH) return;
    int e = (int)(idx / CH);
    int c = ((int)idx % CH) * 4;
    int s = ei[e];
    int d = ei[N_EDGES + e];
    float4 v = *(const float4*)(h + (long long)s * C + c);
    float* p = agg + (long long)d * C + c;
    asm volatile("red.global.add.v4.f32 [%0], {%1,%2,%3,%4};"
                 :: "l"(p), "f"(v.x), "f"(v.y), "f"(v.z), "f"(v.w) : "memory");
}

// ---------------- fused MLP (FFMA2): zout = relu(z@w1+b1)@w2+b2 + BN stats ----------------
// 128x128 tile / block, 256 threads. Accs: 8 rows x 4 col-pairs (f32x2).
template <int CIN>
__global__ __launch_bounds__(256, 2)
void mlp_kernel(const float* __restrict__ zin,
                const float* __restrict__ w1, const float* __restrict__ b1,
                const float* __restrict__ w2, const float* __restrict__ b2,
                float* __restrict__ zout, float* __restrict__ stats) {
    extern __shared__ float sm[];
    float* sz   = sm;                        // 128 * SZ_STR (k-chunk of z)
    float* sh   = sz + 128 * SZ_STR;         // 128 * SH_STR (full hidden tile)
    float* sw   = sh + 128 * SH_STR;         // CK * HID weight chunk
    float* ssum = sw + CK * HID;             // HID
    float* ssq  = ssum + HID;                // HID

    const int tid  = threadIdx.x;
    const int row0 = blockIdx.x * 128;
    const int tx = tid & 15, ty = tid >> 4;
    const int c0 = tx * 4;
    const int c1 = 64 + tx * 4;
    const int r0 = ty * 8;

    if (tid < HID) { ssum[tid] = 0.f; ssq[tid] = 0.f; }

    u64t A[8][4];   // [row][col-pair]: pairs (c0,c0+1),(c0+2,c0+3),(c1,c1+1),(c1+2,c1+3)

    // ======== GEMM1: hidden = relu(z @ w1 + b1) ========
    {
        u64t bA = pk2(b1[c0], b1[c0 + 1]);
        u64t bB = pk2(b1[c0 + 2], b1[c0 + 3]);
        u64t bC = pk2(b1[c1], b1[c1 + 1]);
        u64t bD = pk2(b1[c1 + 2], b1[c1 + 3]);
        #pragma unroll
        for (int i = 0; i < 8; i++) { A[i][0] = bA; A[i][1] = bB; A[i][2] = bC; A[i][3] = bD; }

        const int NKC = CIN / CK;
        for (int kc = 0; kc < NKC; kc++) {
            __syncthreads();
            // stage z chunk: 128 rows x 32 k  (1024 float4)
            #pragma unroll
            for (int t = 0; t < 4; t++) {
                int i = tid + t * 256;
                int r = i >> 3, q = i & 7;
                int gr = row0 + r;
                float4 v = make_float4(0.f, 0.f, 0.f, 0.f);
                if (gr < N_NODES)
                    v = *(const float4*)(zin + (size_t)gr * CIN + kc * CK + q * 4);
                *(float4*)&sz[r * SZ_STR + q * 4] = v;
            }
            // stage w1 chunk: 32 x 128 (1024 float4), contiguous
            #pragma unroll
            for (int t = 0; t < 4; t++) {
                int i = tid + t * 256;
                ((float4*)sw)[i] = ((const float4*)w1)[kc * (CK * HID / 4) + i];
            }
            __syncthreads();
            #pragma unroll 4
            for (int k = 0; k < CK; k++) {
                float zr[8];
                #pragma unroll
                for (int i = 0; i < 8; i++) zr[i] = sz[(r0 + i) * SZ_STR + k];
                ulonglong2 wa = *(const ulonglong2*)&sw[k * HID + c0];
                ulonglong2 wb = *(const ulonglong2*)&sw[k * HID + c1];
                #pragma unroll
                for (int i = 0; i < 8; i++) {
                    u64t zz = pkd(zr[i]);
                    A[i][0] = ffma2(zz, wa.x, A[i][0]);
                    A[i][1] = ffma2(zz, wa.y, A[i][1]);
                    A[i][2] = ffma2(zz, wb.x, A[i][2]);
                    A[i][3] = ffma2(zz, wb.y, A[i][3]);
                }
            }
        }
        // relu + store hidden tile (row-major, vector stores)
        #pragma unroll
        for (int i = 0; i < 8; i++) {
            float v0, v1, v2, v3, v4, v5, v6, v7;
            upk(A[i][0], v0, v1); upk(A[i][1], v2, v3);
            upk(A[i][2], v4, v5); upk(A[i][3], v6, v7);
            *(float4*)&sh[(r0 + i) * SH_STR + c0] =
                make_float4(fmaxf(v0, 0.f), fmaxf(v1, 0.f), fmaxf(v2, 0.f), fmaxf(v3, 0.f));
            *(float4*)&sh[(r0 + i) * SH_STR + c1] =
                make_float4(fmaxf(v4, 0.f), fmaxf(v5, 0.f), fmaxf(v6, 0.f), fmaxf(v7, 0.f));
        }
    }

    // ======== GEMM2: out = hidden @ w2 + b2 ========
    {
        u64t bA = pk2(b2[c0], b2[c0 + 1]);
        u64t bB = pk2(b2[c0 + 2], b2[c0 + 3]);
        u64t bC = pk2(b2[c1], b2[c1 + 1]);
        u64t bD = pk2(b2[c1 + 2], b2[c1 + 3]);
        #pragma unroll
        for (int i = 0; i < 8; i++) { A[i][0] = bA; A[i][1] = bB; A[i][2] = bC; A[i][3] = bD; }

        for (int kc = 0; kc < HID / CK; kc++) {
            __syncthreads();   // sh writes done (kc=0) / prev w2 chunk consumed
            #pragma unroll
            for (int t = 0; t < 4; t++) {
                int i = tid + t * 256;
                ((float4*)sw)[i] = ((const float4*)w2)[kc * (CK * HID / 4) + i];
            }
            __syncthreads();
            #pragma unroll 4
            for (int k = 0; k < CK; k++) {
                int kk = kc * CK + k;
                float hr[8];
                #pragma unroll
                for (int i = 0; i < 8; i++) hr[i] = sh[(r0 + i) * SH_STR + kk];
                ulonglong2 wa = *(const ulonglong2*)&sw[k * HID + c0];
                ulonglong2 wb = *(const ulonglong2*)&sw[k * HID + c1];
                #pragma unroll
                for (int i = 0; i < 8; i++) {
                    u64t hh = pkd(hr[i]);
                    A[i][0] = ffma2(hh, wa.x, A[i][0]);
                    A[i][1] = ffma2(hh, wa.y, A[i][1]);
                    A[i][2] = ffma2(hh, wb.x, A[i][2]);
                    A[i][3] = ffma2(hh, wb.y, A[i][3]);
                }
            }
        }
    }

    // ======== epilogue: store pre-BN z, accumulate BN column stats ========
    float s[8], q[8];
    #pragma unroll
    for (int j = 0; j < 8; j++) { s[j] = 0.f; q[j] = 0.f; }

    #pragma unroll
    for (int i = 0; i < 8; i++) {
        int gr = row0 + r0 + i;
        if (gr < N_NODES) {
            float v[8];
            upk(A[i][0], v[0], v[1]); upk(A[i][1], v[2], v[3]);
            upk(A[i][2], v[4], v[5]); upk(A[i][3], v[6], v[7]);
            *(float4*)&zout[(size_t)gr * HID + c0] = make_float4(v[0], v[1], v[2], v[3]);
            *(float4*)&zout[(size_t)gr * HID + c1] = make_float4(v[4], v[5], v[6], v[7]);
            #pragma unroll
            for (int j = 0; j < 8; j++) { s[j] += v[j]; q[j] += v[j] * v[j]; }
        }
    }
    #pragma unroll
    for (int j = 0; j < 4; j++) {
        atomicAdd(&ssum[c0 + j], s[j]);
        atomicAdd(&ssq[c0 + j], q[j]);
        atomicAdd(&ssum[c1 + j], s[4 + j]);
        atomicAdd(&ssq[c1 + j], q[4 + j]);
    }
    __syncthreads();
    if (tid < HID) {
        atomicAdd(&stats[tid], ssum[tid]);
        atomicAdd(&stats[HID + tid], ssq[tid]);
    }
}

// ---------------- BN finalize ----------------
__global__ void bn_finalize_kernel(const float* __restrict__ gamma,
                                   const float* __restrict__ beta,
                                   const float* __restrict__ stats,
                                   float* __restrict__ scale,
                                   float* __restrict__ shift) {
    int c = threadIdx.x;
    float mean = stats[c] * (1.f / N_NODES);
    float var  = stats[HID + c] * (1.f / N_NODES) - mean * mean;
    float inv  = rsqrtf(var + BN_EPS);
    float sc   = gamma[c] * inv;
    scale[c] = sc;
    shift[c] = beta[c] - mean * sc;
}

// ---------------- BN apply + relu; optional copy into agg buffer ----------------
__global__ void bn_apply_kernel(const float4* __restrict__ z, float4* __restrict__ h,
                                float4* __restrict__ agg, int writeAgg,
                                const float* __restrict__ scale,
                                const float* __restrict__ shift) {
    int idx = blockIdx.x * blockDim.x + threadIdx.x;
    if (idx >= N_NODES * HID / 4) return;
    int c4 = (idx & 31) * 4;
    float4 v = z[idx];
    v.x = fmaxf(fmaf(v.x, scale[c4 + 0], shift[c4 + 0]), 0.f);
    v.y = fmaxf(fmaf(v.y, scale[c4 + 1], shift[c4 + 1]), 0.f);
    v.z = fmaxf(fmaf(v.z, scale[c4 + 2], shift[c4 + 2]), 0.f);
    v.w = fmaxf(fmaf(v.w, scale[c4 + 3], shift[c4 + 3]), 0.f);
    h[idx] = v;
    if (writeAgg) agg[idx] = v;
}

// ---------------- mean pool (batch sorted) ----------------
__global__ void pool_kernel(const float* __restrict__ h, const int* __restrict__ batch,
                            float* __restrict__ pool) {
    __shared__ int sb[256];
    int r0  = blockIdx.x * 256;
    int tid = threadIdx.x;  // 128 threads = one column each
    for (int i = tid; i < 256; i += 128) {
        int gr = r0 + i;
        sb[i] = (gr < N_NODES) ? batch[gr] : -1;
    }
    __syncthreads();
    int c = tid;
    float sum = 0.f;
    int cur = sb[0];
    for (int i = 0; i < 256; i++) {
        int gr = r0 + i;
        if (gr >= N_NODES) break;
        int b = sb[i];
        if (b != cur) {
            atomicAdd(&pool[cur * HID + c], sum);
            sum = 0.f; cur = b;
        }
        sum += h[(long long)gr * HID + c];
    }
    if (cur >= 0) atomicAdd(&pool[cur * HID + c], sum);
}

// ---------------- per-graph counts via binary search ----------------
__global__ void count_kernel(const int* __restrict__ batch, float* __restrict__ cinv) {
    int g = threadIdx.x;
    int lo = 0, hi = N_NODES;
    while (lo < hi) { int m = (lo + hi) >> 1; if (batch[m] < g) lo = m + 1; else hi = m; }
    int a = lo;
    lo = 0; hi = N_NODES;
    while (lo < hi) { int m = (lo + hi) >> 1; if (batch[m] < g + 1) lo = m + 1; else hi = m; }
    float cnt = (float)(lo - a);
    cinv[g] = 1.f / fmaxf(cnt, 1.f);
}

// ---------------- final projection ----------------
__global__ void proj_kernel(const float* __restrict__ w, const float* __restrict__ b,
                            const float* __restrict__ pool, const float* __restrict__ cinv,
                            float* __restrict__ out) {
    __shared__ float hg[HID];
    int g = blockIdx.x, t = threadIdx.x;
    hg[t] = pool[g * HID + t] * cinv[g];
    __syncthreads();
    float acc = b[t];
    #pragma unroll 8
    for (int k = 0; k < HID; k++) acc = fmaf(hg[k], w[k * HID + t], acc);
    out[g * HID + t] = acc;
}

// ---------------- host orchestration ----------------
static void* sym(const void* s) {
    void* p = nullptr;
    cudaGetSymbolAddress(&p, s);
    return p;
}

extern "C" void kernel_launch(void* const* d_in, const int* in_sizes, int n_in,
                              void* d_out, int out_size) {
    const float* x     = (const float*)d_in[0];
    const int*   ei    = (const int*)d_in[1];
    const int*   batch = (const int*)d_in[2];
    const float* L[3][6];
    for (int l = 0; l < 3; l++)
        for (int k = 0; k < 6; k++) L[l][k] = (const float*)d_in[3 + 6 * l + k];
    const float* proj_w = (const float*)d_in[21];
    const float* proj_b = (const float*)d_in[22];
    float* out = (float*)d_out;

    float* H     = (float*)sym(g_H);
    float* AGG   = (float*)sym(g_AGG);
    float* Z     = (float*)sym(g_Z);
    float* STATS = (float*)sym(g_STATS);
    float* SCALE = (float*)sym(g_SCALE);
    float* SHIFT = (float*)sym(g_SHIFT);
    float* POOL  = (float*)sym(g_POOL);
    float* CINV  = (float*)sym(g_CINV);

    const int smemMlp = (128 * SZ_STR + 128 * SH_STR + CK * HID + 2 * HID) * 4;
    cudaFuncSetAttribute(mlp_kernel<IN_C>, cudaFuncAttributeMaxDynamicSharedMemorySize, smemMlp);
    cudaFuncSetAttribute(mlp_kernel<HID>,  cudaFuncAttributeMaxDynamicSharedMemorySize, smemMlp);

    const int mlpBlocks = (N_NODES + 127) / 128;
    const int applyN4   = N_NODES * HID / 4;

    // ---- layer 0 (CIN=64): AGG = x; AGG += scatter(x) ----
    {
        int n4 = N_NODES * IN_C / 4;
        copy4_kernel<<<(n4 + 255) / 256, 256>>>((float4*)AGG, (const float4*)x, n4);
        long long sthreads = (long long)N_EDGES * (IN_C / 4);
        scatter_kernel<IN_C><<<(int)((sthreads + 255) / 256), 256>>>(ei, x, AGG);
        zero_kernel<<<1, 256>>>(STATS, 2 * HID);
        mlp_kernel<IN_C><<<mlpBlocks, 256, smemMlp>>>(AGG, L[0][0], L[0][1], L[0][2], L[0][3], Z, STATS);
        bn_finalize_kernel<<<1, HID>>>(L[0][4], L[0][5], STATS, SCALE, SHIFT);
        bn_apply_kernel<<<(applyN4 + 255) / 256, 256>>>((const float4*)Z, (float4*)H, (float4*)AGG, 1, SCALE, SHIFT);
    }

    // ---- layers 1,2 (CIN=128) ----
    for (int l = 1; l < 3; l++) {
        long long sthreads = (long long)N_EDGES * (HID / 4);
        scatter_kernel<HID><<<(int)((sthreads + 255) / 256), 256>>>(ei, H, AGG);
        zero_kernel<<<1, 256>>>(STATS, 2 * HID);
        mlp_kernel<HID><<<mlpBlocks, 256, smemMlp>>>(AGG, L[l][0], L[l][1], L[l][2], L[l][3], Z, STATS);
        bn_finalize_kernel<<<1, HID>>>(L[l][4], L[l][5], STATS, SCALE, SHIFT);
        int writeAgg = (l < 2) ? 1 : 0;
        bn_apply_kernel<<<(applyN4 + 255) / 256, 256>>>((const float4*)Z, (float4*)H, (float4*)AGG, writeAgg, SCALE, SHIFT);
    }

    // ---- pool + projection ----
    zero_kernel<<<(N_GRAPHS * HID + 255) / 256, 256>>>(POOL, N_GRAPHS * HID);
    pool_kernel<<<(N_NODES + 255) / 256, 128>>>(H, batch, POOL);
    count_kernel<<<1, N_GRAPHS>>>(batch, CINV);
    proj_kernel<<<N_GRAPHS, HID>>>(proj_w, proj_b, POOL, CINV, out);
}

// round 6
// speedup vs baseline: 1.5667x; 1.4719x over previous
#include <cuda_runtime.h>
#include <cstdint>

#define N_NODES 100000
#define N_EDGES 1600000
#define N_GRAPHS 256
#define IN_C 64
#define HID 128
#define BN_EPS 1e-5f
#define CK 32           // k-chunk
#define SZ_STR 36       // z-chunk row stride (floats)
#define SH_STR 132      // hidden row stride (floats)
#define SCAN_BLKS ((N_NODES + 255) / 256)   // 391

typedef unsigned long long u64t;

// ---- packed fp32x2 helpers (FFMA2 — only reachable via PTX) ----
__device__ __forceinline__ u64t pk2(float lo, float hi) {
    u64t r; asm("mov.b64 %0,{%1,%2};" : "=l"(r) : "f"(lo), "f"(hi)); return r;
}
__device__ __forceinline__ u64t pkd(float v) {
    u64t r; asm("mov.b64 %0,{%1,%1};" : "=l"(r) : "f"(v)); return r;
}
__device__ __forceinline__ void upk(u64t p, float& lo, float& hi) {
    asm("mov.b64 {%0,%1},%2;" : "=f"(lo), "=f"(hi) : "l"(p));
}
__device__ __forceinline__ u64t ffma2(u64t a, u64t b, u64t c) {
    u64t d; asm("fma.rn.f32x2 %0,%1,%2,%3;" : "=l"(d) : "l"(a), "l"(b), "l"(c)); return d;
}

// ---------------- scratch (device globals; no allocation) ----------------
__device__ float g_Z0[(size_t)N_NODES * HID];
__device__ float g_Z1[(size_t)N_NODES * HID];
__device__ float g_AGG[(size_t)N_NODES * HID];
__device__ float g_STATS[2 * HID];
__device__ float g_SCALE[3 * HID];
__device__ float g_SHIFT[3 * HID];
__device__ float g_POOL[N_GRAPHS * HID];
__device__ float g_CINV[N_GRAPHS];
__device__ int   g_DEG[N_NODES];
__device__ int   g_OFFS[N_NODES];
__device__ int   g_CURS[N_NODES];
__device__ int   g_BSUM[SCAN_BLKS];
__device__ int   g_CSR[N_EDGES];

// ---------------- small utility kernels ----------------
__global__ void zero_kernel(float* p, int n) {
    int i = blockIdx.x * blockDim.x + threadIdx.x;
    if (i < n) p[i] = 0.f;
}
__global__ void zeroi_kernel(int* p, int n) {
    int i = blockIdx.x * blockDim.x + threadIdx.x;
    if (i < n) p[i] = 0;
}

// ================= CSR build =================
__global__ void hist_kernel(const int* __restrict__ ei, int* __restrict__ deg) {
    int e = blockIdx.x * blockDim.x + threadIdx.x;
    if (e < N_EDGES) atomicAdd(&deg[ei[N_EDGES + e]], 1);
}

// per-block exclusive scan of deg; block total -> bsum
__global__ void scan_block_kernel(const int* __restrict__ deg,
                                  int* __restrict__ offs, int* __restrict__ bsum) {
    __shared__ int s[256];
    int tid = threadIdx.x;
    int i = blockIdx.x * 256 + tid;
    int v = (i < N_NODES) ? deg[i] : 0;
    s[tid] = v;
    __syncthreads();
    #pragma unroll
    for (int d = 1; d < 256; d <<= 1) {
        int t = (tid >= d) ? s[tid - d] : 0;
        __syncthreads();
        s[tid] += t;
        __syncthreads();
    }
    if (i < N_NODES) offs[i] = s[tid] - v;   // exclusive
    if (tid == 255) bsum[blockIdx.x] = s[255];
}

// scan block sums in-place (exclusive), single block of 512
__global__ void scan_bsum_kernel(int* __restrict__ bsum) {
    __shared__ int s[512];
    int tid = threadIdx.x;
    int v = (tid < SCAN_BLKS) ? bsum[tid] : 0;
    s[tid] = v;
    __syncthreads();
    #pragma unroll
    for (int d = 1; d < 512; d <<= 1) {
        int t = (tid >= d) ? s[tid - d] : 0;
        __syncthreads();
        s[tid] += t;
        __syncthreads();
    }
    if (tid < SCAN_BLKS) bsum[tid] = s[tid] - v;
}

__global__ void scan_add_kernel(int* __restrict__ offs, const int* __restrict__ bsum,
                                int* __restrict__ curs) {
    int i = blockIdx.x * 256 + threadIdx.x;
    if (i < N_NODES) {
        int o = offs[i] + bsum[blockIdx.x];
        offs[i] = o;
        curs[i] = o;
    }
}

__global__ void fill_kernel(const int* __restrict__ ei, int* __restrict__ curs,
                            int* __restrict__ csr) {
    int e = blockIdx.x * blockDim.x + threadIdx.x;
    if (e < N_EDGES) {
        int d = ei[N_EDGES + e];
        int slot = atomicAdd(&curs[d], 1);
        csr[slot] = ei[e];
    }
}

// ================= gather-aggregate (atomic-free, BN fused) =================
// z_in[dst] = bnrelu?(z[dst]) + sum_{s in N(dst)} bnrelu?(z[s]); warp per node.
__global__ __launch_bounds__(256)
void gather64_kernel(const int* __restrict__ deg, const int* __restrict__ offs,
                     const int* __restrict__ csr, const float* __restrict__ z,
                     float* __restrict__ outz) {
    int node = (blockIdx.x * 256 + threadIdx.x) >> 5;
    if (node >= N_NODES) return;
    int lane = threadIdx.x & 31;
    int c = lane * 2;
    float2 acc = *(const float2*)(z + (size_t)node * IN_C + c);
    int beg = offs[node], n = deg[node];
    int e = 0;
    for (; e + 2 <= n; e += 2) {
        int s0 = csr[beg + e], s1 = csr[beg + e + 1];
        float2 v0 = *(const float2*)(z + (size_t)s0 * IN_C + c);
        float2 v1 = *(const float2*)(z + (size_t)s1 * IN_C + c);
        acc.x += v0.x + v1.x;
        acc.y += v0.y + v1.y;
    }
    if (e < n) {
        int s0 = csr[beg + e];
        float2 v0 = *(const float2*)(z + (size_t)s0 * IN_C + c);
        acc.x += v0.x; acc.y += v0.y;
    }
    *(float2*)(outz + (size_t)node * IN_C + c) = acc;
}

__global__ __launch_bounds__(256)
void gather128_kernel(const int* __restrict__ deg, const int* __restrict__ offs,
                      const int* __restrict__ csr, const float* __restrict__ z,
                      const float* __restrict__ scale, const float* __restrict__ shift,
                      float* __restrict__ outz) {
    int node = (blockIdx.x * 256 + threadIdx.x) >> 5;
    if (node >= N_NODES) return;
    int lane = threadIdx.x & 31;
    int c = lane * 4;
    float4 sc = *(const float4*)(scale + c);
    float4 sh = *(const float4*)(shift + c);

    float4 v = *(const float4*)(z + (size_t)node * HID + c);
    float4 acc;
    acc.x = fmaxf(fmaf(v.x, sc.x, sh.x), 0.f);
    acc.y = fmaxf(fmaf(v.y, sc.y, sh.y), 0.f);
    acc.z = fmaxf(fmaf(v.z, sc.z, sh.z), 0.f);
    acc.w = fmaxf(fmaf(v.w, sc.w, sh.w), 0.f);

    int beg = offs[node], n = deg[node];
    int e = 0;
    for (; e + 2 <= n; e += 2) {
        int s0 = csr[beg + e], s1 = csr[beg + e + 1];
        float4 v0 = *(const float4*)(z + (size_t)s0 * HID + c);
        float4 v1 = *(const float4*)(z + (size_t)s1 * HID + c);
        acc.x += fmaxf(fmaf(v0.x, sc.x, sh.x), 0.f) + fmaxf(fmaf(v1.x, sc.x, sh.x), 0.f);
        acc.y += fmaxf(fmaf(v0.y, sc.y, sh.y), 0.f) + fmaxf(fmaf(v1.y, sc.y, sh.y), 0.f);
        acc.z += fmaxf(fmaf(v0.z, sc.z, sh.z), 0.f) + fmaxf(fmaf(v1.z, sc.z, sh.z), 0.f);
        acc.w += fmaxf(fmaf(v0.w, sc.w, sh.w), 0.f) + fmaxf(fmaf(v1.w, sc.w, sh.w), 0.f);
    }
    if (e < n) {
        int s0 = csr[beg + e];
        float4 v0 = *(const float4*)(z + (size_t)s0 * HID + c);
        acc.x += fmaxf(fmaf(v0.x, sc.x, sh.x), 0.f);
        acc.y += fmaxf(fmaf(v0.y, sc.y, sh.y), 0.f);
        acc.z += fmaxf(fmaf(v0.z, sc.z, sh.z), 0.f);
        acc.w += fmaxf(fmaf(v0.w, sc.w, sh.w), 0.f);
    }
    *(float4*)(outz + (size_t)node * HID + c) = acc;
}

// ---------------- fused MLP (FFMA2): zout = relu(z@w1+b1)@w2+b2 + BN stats ----------------
template <int CIN>
__global__ __launch_bounds__(256, 2)
void mlp_kernel(const float* __restrict__ zin,
                const float* __restrict__ w1, const float* __restrict__ b1,
                const float* __restrict__ w2, const float* __restrict__ b2,
                float* __restrict__ zout, float* __restrict__ stats) {
    extern __shared__ float sm[];
    float* sz   = sm;                        // 128 * SZ_STR
    float* sh   = sz + 128 * SZ_STR;         // 128 * SH_STR
    float* sw   = sh + 128 * SH_STR;         // CK * HID
    float* ssum = sw + CK * HID;             // HID
    float* ssq  = ssum + HID;                // HID

    const int tid  = threadIdx.x;
    const int row0 = blockIdx.x * 128;
    const int tx = tid & 15, ty = tid >> 4;
    const int c0 = tx * 4;
    const int c1 = 64 + tx * 4;
    const int r0 = ty * 8;

    if (tid < HID) { ssum[tid] = 0.f; ssq[tid] = 0.f; }

    u64t A[8][4];

    // ======== GEMM1 ========
    {
        u64t bA = pk2(b1[c0], b1[c0 + 1]);
        u64t bB = pk2(b1[c0 + 2], b1[c0 + 3]);
        u64t bC = pk2(b1[c1], b1[c1 + 1]);
        u64t bD = pk2(b1[c1 + 2], b1[c1 + 3]);
        #pragma unroll
        for (int i = 0; i < 8; i++) { A[i][0] = bA; A[i][1] = bB; A[i][2] = bC; A[i][3] = bD; }

        const int NKC = CIN / CK;
        for (int kc = 0; kc < NKC; kc++) {
            __syncthreads();
            #pragma unroll
            for (int t = 0; t < 4; t++) {
                int i = tid + t * 256;
                int r = i >> 3, q = i & 7;
                int gr = row0 + r;
                float4 v = make_float4(0.f, 0.f, 0.f, 0.f);
                if (gr < N_NODES)
                    v = *(const float4*)(zin + (size_t)gr * CIN + kc * CK + q * 4);
                *(float4*)&sz[r * SZ_STR + q * 4] = v;
            }
            #pragma unroll
            for (int t = 0; t < 4; t++) {
                int i = tid + t * 256;
                ((float4*)sw)[i] = ((const float4*)w1)[kc * (CK * HID / 4) + i];
            }
            __syncthreads();
            #pragma unroll 4
            for (int k = 0; k < CK; k++) {
                float zr[8];
                #pragma unroll
                for (int i = 0; i < 8; i++) zr[i] = sz[(r0 + i) * SZ_STR + k];
                ulonglong2 wa = *(const ulonglong2*)&sw[k * HID + c0];
                ulonglong2 wb = *(const ulonglong2*)&sw[k * HID + c1];
                #pragma unroll
                for (int i = 0; i < 8; i++) {
                    u64t zz = pkd(zr[i]);
                    A[i][0] = ffma2(zz, wa.x, A[i][0]);
                    A[i][1] = ffma2(zz, wa.y, A[i][1]);
                    A[i][2] = ffma2(zz, wb.x, A[i][2]);
                    A[i][3] = ffma2(zz, wb.y, A[i][3]);
                }
            }
        }
        #pragma unroll
        for (int i = 0; i < 8; i++) {
            float v0, v1, v2, v3, v4, v5, v6, v7;
            upk(A[i][0], v0, v1); upk(A[i][1], v2, v3);
            upk(A[i][2], v4, v5); upk(A[i][3], v6, v7);
            *(float4*)&sh[(r0 + i) * SH_STR + c0] =
                make_float4(fmaxf(v0, 0.f), fmaxf(v1, 0.f), fmaxf(v2, 0.f), fmaxf(v3, 0.f));
            *(float4*)&sh[(r0 + i) * SH_STR + c1] =
                make_float4(fmaxf(v4, 0.f), fmaxf(v5, 0.f), fmaxf(v6, 0.f), fmaxf(v7, 0.f));
        }
    }

    // ======== GEMM2 ========
    {
        u64t bA = pk2(b2[c0], b2[c0 + 1]);
        u64t bB = pk2(b2[c0 + 2], b2[c0 + 3]);
        u64t bC = pk2(b2[c1], b2[c1 + 1]);
        u64t bD = pk2(b2[c1 + 2], b2[c1 + 3]);
        #pragma unroll
        for (int i = 0; i < 8; i++) { A[i][0] = bA; A[i][1] = bB; A[i][2] = bC; A[i][3] = bD; }

        for (int kc = 0; kc < HID / CK; kc++) {
            __syncthreads();
            #pragma unroll
            for (int t = 0; t < 4; t++) {
                int i = tid + t * 256;
                ((float4*)sw)[i] = ((const float4*)w2)[kc * (CK * HID / 4) + i];
            }
            __syncthreads();
            #pragma unroll 4
            for (int k = 0; k < CK; k++) {
                int kk = kc * CK + k;
                float hr[8];
                #pragma unroll
                for (int i = 0; i < 8; i++) hr[i] = sh[(r0 + i) * SH_STR + kk];
                ulonglong2 wa = *(const ulonglong2*)&sw[k * HID + c0];
                ulonglong2 wb = *(const ulonglong2*)&sw[k * HID + c1];
                #pragma unroll
                for (int i = 0; i < 8; i++) {
                    u64t hh = pkd(hr[i]);
                    A[i][0] = ffma2(hh, wa.x, A[i][0]);
                    A[i][1] = ffma2(hh, wa.y, A[i][1]);
                    A[i][2] = ffma2(hh, wb.x, A[i][2]);
                    A[i][3] = ffma2(hh, wb.y, A[i][3]);
                }
            }
        }
    }

    // ======== epilogue ========
    float s[8], q[8];
    #pragma unroll
    for (int j = 0; j < 8; j++) { s[j] = 0.f; q[j] = 0.f; }

    #pragma unroll
    for (int i = 0; i < 8; i++) {
        int gr = row0 + r0 + i;
        if (gr < N_NODES) {
            float v[8];
            upk(A[i][0], v[0], v[1]); upk(A[i][1], v[2], v[3]);
            upk(A[i][2], v[4], v[5]); upk(A[i][3], v[6], v[7]);
            *(float4*)&zout[(size_t)gr * HID + c0] = make_float4(v[0], v[1], v[2], v[3]);
            *(float4*)&zout[(size_t)gr * HID + c1] = make_float4(v[4], v[5], v[6], v[7]);
            #pragma unroll
            for (int j = 0; j < 8; j++) { s[j] += v[j]; q[j] += v[j] * v[j]; }
        }
    }
    #pragma unroll
    for (int j = 0; j < 4; j++) {
        atomicAdd(&ssum[c0 + j], s[j]);
        atomicAdd(&ssq[c0 + j], q[j]);
        atomicAdd(&ssum[c1 + j], s[4 + j]);
        atomicAdd(&ssq[c1 + j], q[4 + j]);
    }
    __syncthreads();
    if (tid < HID) {
        atomicAdd(&stats[tid], ssum[tid]);
        atomicAdd(&stats[HID + tid], ssq[tid]);
    }
}

// ---------------- BN finalize ----------------
__global__ void bn_finalize_kernel(const float* __restrict__ gamma,
                                   const float* __restrict__ beta,
                                   const float* __restrict__ stats,
                                   float* __restrict__ scale,
                                   float* __restrict__ shift) {
    int c = threadIdx.x;
    float mean = stats[c] * (1.f / N_NODES);
    float var  = stats[HID + c] * (1.f / N_NODES) - mean * mean;
    float inv  = rsqrtf(var + BN_EPS);
    float sc   = gamma[c] * inv;
    scale[c] = sc;
    shift[c] = beta[c] - mean * sc;
}

// ---------------- mean pool with fused BN+relu (batch sorted) ----------------
__global__ void pool_kernel(const float* __restrict__ z, const int* __restrict__ batch,
                            const float* __restrict__ scale, const float* __restrict__ shift,
                            float* __restrict__ pool) {
    __shared__ int sb[256];
    int r0  = blockIdx.x * 256;
    int tid = threadIdx.x;  // 128 threads, one column each
    for (int i = tid; i < 256; i += 128) {
        int gr = r0 + i;
        sb[i] = (gr < N_NODES) ? batch[gr] : -1;
    }
    __syncthreads();
    int c = tid;
    float sc = scale[c], sh = shift[c];
    float sum = 0.f;
    int cur = sb[0];
    for (int i = 0; i < 256; i++) {
        int gr = r0 + i;
        if (gr >= N_NODES) break;
        int b = sb[i];
        if (b != cur) {
            atomicAdd(&pool[cur * HID + c], sum);
            sum = 0.f; cur = b;
        }
        sum += fmaxf(fmaf(z[(long long)gr * HID + c], sc, sh), 0.f);
    }
    if (cur >= 0) atomicAdd(&pool[cur * HID + c], sum);
}

// ---------------- per-graph counts via binary search ----------------
__global__ void count_kernel(const int* __restrict__ batch, float* __restrict__ cinv) {
    int g = threadIdx.x;
    int lo = 0, hi = N_NODES;
    while (lo < hi) { int m = (lo + hi) >> 1; if (batch[m] < g) lo = m + 1; else hi = m; }
    int a = lo;
    lo = 0; hi = N_NODES;
    while (lo < hi) { int m = (lo + hi) >> 1; if (batch[m] < g + 1) lo = m + 1; else hi = m; }
    float cnt = (float)(lo - a);
    cinv[g] = 1.f / fmaxf(cnt, 1.f);
}

// ---------------- final projection ----------------
__global__ void proj_kernel(const float* __restrict__ w, const float* __restrict__ b,
                            const float* __restrict__ pool, const float* __restrict__ cinv,
                            float* __restrict__ out) {
    __shared__ float hg[HID];
    int g = blockIdx.x, t = threadIdx.x;
    hg[t] = pool[g * HID + t] * cinv[g];
    __syncthreads();
    float acc = b[t];
    #pragma unroll 8
    for (int k = 0; k < HID; k++) acc = fmaf(hg[k], w[k * HID + t], acc);
    out[g * HID + t] = acc;
}

// ---------------- host orchestration ----------------
static void* sym(const void* s) {
    void* p = nullptr;
    cudaGetSymbolAddress(&p, s);
    return p;
}

extern "C" void kernel_launch(void* const* d_in, const int* in_sizes, int n_in,
                              void* d_out, int out_size) {
    const float* x     = (const float*)d_in[0];
    const int*   ei    = (const int*)d_in[1];
    const int*   batch = (const int*)d_in[2];
    const float* L[3][6];
    for (int l = 0; l < 3; l++)
        for (int k = 0; k < 6; k++) L[l][k] = (const float*)d_in[3 + 6 * l + k];
    const float* proj_w = (const float*)d_in[21];
    const float* proj_b = (const float*)d_in[22];
    float* out = (float*)d_out;

    float* Z0    = (float*)sym(g_Z0);
    float* Z1    = (float*)sym(g_Z1);
    float* AGG   = (float*)sym(g_AGG);
    float* STATS = (float*)sym(g_STATS);
    float* SCALE = (float*)sym(g_SCALE);
    float* SHIFT = (float*)sym(g_SHIFT);
    float* POOL  = (float*)sym(g_POOL);
    float* CINV  = (float*)sym(g_CINV);
    int*   DEG   = (int*)sym(g_DEG);
    int*   OFFS  = (int*)sym(g_OFFS);
    int*   CURS  = (int*)sym(g_CURS);
    int*   BSUM  = (int*)sym(g_BSUM);
    int*   CSR   = (int*)sym(g_CSR);

    const int smemMlp = (128 * SZ_STR + 128 * SH_STR + CK * HID + 2 * HID) * 4;
    cudaFuncSetAttribute(mlp_kernel<IN_C>, cudaFuncAttributeMaxDynamicSharedMemorySize, smemMlp);
    cudaFuncSetAttribute(mlp_kernel<HID>,  cudaFuncAttributeMaxDynamicSharedMemorySize, smemMlp);

    const int mlpBlocks  = (N_NODES + 127) / 128;
    const int edgeBlocks = (N_EDGES + 255) / 256;
    const int gathBlocks = (N_NODES * 32 + 255) / 256;   // warp per node

    // ---- CSR build (reused by all 3 layers) ----
    zeroi_kernel<<<SCAN_BLKS, 256>>>(DEG, N_NODES);
    hist_kernel<<<edgeBlocks, 256>>>(ei, DEG);
    scan_block_kernel<<<SCAN_BLKS, 256>>>(DEG, OFFS, BSUM);
    scan_bsum_kernel<<<1, 512>>>(BSUM);
    scan_add_kernel<<<SCAN_BLKS, 256>>>(OFFS, BSUM, CURS);
    fill_kernel<<<edgeBlocks, 256>>>(ei, CURS, CSR);

    // ---- layer 0 (CIN=64): z_in = x + sum_N x ----
    gather64_kernel<<<gathBlocks, 256>>>(DEG, OFFS, CSR, x, AGG);
    zero_kernel<<<1, 256>>>(STATS, 2 * HID);
    mlp_kernel<IN_C><<<mlpBlocks, 256, smemMlp>>>(
        AGG, L[0][0], L[0][1], L[0][2], L[0][3], Z0, STATS);
    bn_finalize_kernel<<<1, HID>>>(L[0][4], L[0][5], STATS, SCALE, SHIFT);

    // ---- layers 1,2 (CIN=128), BN of previous layer fused into gather ----
    const float* zprev = Z0;
    float* zcur = Z1;
    for (int l = 1; l < 3; l++) {
        const float* sc = SCALE + (l - 1) * HID;
        const float* sh = SHIFT + (l - 1) * HID;
        gather128_kernel<<<gathBlocks, 256>>>(DEG, OFFS, CSR, zprev, sc, sh, AGG);
        zero_kernel<<<1, 256>>>(STATS, 2 * HID);
        mlp_kernel<HID><<<mlpBlocks, 256, smemMlp>>>(
            AGG, L[l][0], L[l][1], L[l][2], L[l][3], zcur, STATS);
        bn_finalize_kernel<<<1, HID>>>(L[l][4], L[l][5], STATS, SCALE + l * HID, SHIFT + l * HID);
        const float* t = zprev; zprev = zcur; zcur = (float*)t;
    }

    // ---- pool + projection (BN of layer 2 fused into pool) ----
    zero_kernel<<<(N_GRAPHS * HID + 255) / 256, 256>>>(POOL, N_GRAPHS * HID);
    pool_kernel<<<(N_NODES + 255) / 256, 128>>>(zprev, batch, SCALE + 2 * HID, SHIFT + 2 * HID, POOL);
    count_kernel<<<1, N_GRAPHS>>>(batch, CINV);
    proj_kernel<<<N_GRAPHS, HID>>>(proj_w, proj_b, POOL, CINV, out);
}